// round 1
// baseline (speedup 1.0000x reference)
#include <cuda_runtime.h>
#include <math.h>

#define NB 32
#define NT 1024
#define ND 512
#define NN 16
#define NDEPTH 3
#define NCHUNK 16
#define TC (NT / NCHUNK)   // 64 timesteps per partial-sum chunk
#define TT 32              // timesteps per output block

// Scratch (static device globals — no allocation)
__device__ float g_partial[NB * NCHUNK * ND];      // 1 MB partial sums
__device__ float g_A[NDEPTH * NB * ND];            // per-depth additive offset c_d[b,:]
__device__ float g_S[NDEPTH * NB * ND];            // per-depth scale sel_d[b,:]

// ---------------------------------------------------------------------------
// Kernel 1: partial sums of x over T (deterministic fixed-order, no atomics).
// grid = NB*NCHUNK blocks, 128 threads; each thread owns a float4 dim-group.
// ---------------------------------------------------------------------------
__global__ void pool_kernel(const float* __restrict__ x) {
    int blk = blockIdx.x;               // b * NCHUNK + chunk
    int b = blk / NCHUNK;
    int c = blk % NCHUNK;
    int g = threadIdx.x;                // 0..127 (float4 group over DIM)
    const float4* xp = (const float4*)(x) + ((size_t)b * NT + (size_t)c * TC) * (ND / 4);
    float4 acc = make_float4(0.f, 0.f, 0.f, 0.f);
#pragma unroll 8
    for (int t = 0; t < TC; ++t) {
        float4 v = xp[(size_t)t * (ND / 4) + g];
        acc.x += v.x; acc.y += v.y; acc.z += v.z; acc.w += v.w;
    }
    ((float4*)g_partial)[(size_t)blk * (ND / 4) + g] = acc;
}

// ---------------------------------------------------------------------------
// Kernel 2: per-batch decision chain. grid = NB blocks, 512 threads (= DIM).
// Sequential over DEPTH: logits -> softmax -> log+gumbel argmax -> route.
// Stores per-depth offset (A) and scale (S) vectors.
// ---------------------------------------------------------------------------
__global__ void decide_kernel(const float* __restrict__ kd0,
                              const float* __restrict__ kd1,
                              const float* __restrict__ kd2,
                              const float* __restrict__ vd0,
                              const float* __restrict__ vd1,
                              const float* __restrict__ vd2,
                              const float* __restrict__ W,
                              const float* __restrict__ gum) {
    int b = blockIdx.x;
    int i = threadIdx.x;                // 0..511 (dim)
    int lane = i & 31;
    int wid = i >> 5;                   // 0..15 (one warp per node n)

    __shared__ float sp[ND];
    __shared__ float slog[NN];
    __shared__ int   sik;

    // pooled_base[b,i] = mean_t x[b,t,i]  (fixed-order chunk sum)
    float pooled = 0.f;
#pragma unroll
    for (int c = 0; c < NCHUNK; ++c)
        pooled += g_partial[(size_t)(b * NCHUNK + c) * ND + i];
    pooled *= (1.0f / NT);

    const float* kds[NDEPTH] = {kd0, kd1, kd2};
    const float* vds[NDEPTH] = {vd0, vd1, vd2};

    float cacc = 0.f;   // cumulative W-row offset for this dim
    int node = 0;
    int ik = 0;

    for (int d = 0; d < NDEPTH; ++d) {
        if (d > 0) cacc += W[(size_t)ik * ND + i];
        sp[i] = pooled + cacc;
        __syncthreads();

        // warp `wid` computes logits[wid] = dot(sp, keys[d][node, wid, :])
        const float* krow = kds[d] + ((size_t)node * NN + wid) * ND;
        float s = 0.f;
#pragma unroll
        for (int j = lane; j < ND; j += 32) s += sp[j] * krow[j];
#pragma unroll
        for (int o = 16; o; o >>= 1) s += __shfl_down_sync(0xffffffffu, s, o);
        if (lane == 0) slog[wid] = s;
        __syncthreads();

        if (i == 0) {
            // softmax over NN, then argmax(log(prob) + gumbel) — first-max wins (matches jnp.argmax)
            float m = slog[0];
#pragma unroll
            for (int n = 1; n < NN; ++n) m = fmaxf(m, slog[n]);
            float e[NN];
            float es = 0.f;
#pragma unroll
            for (int n = 0; n < NN; ++n) { e[n] = expf(slog[n] - m); es += e[n]; }
            int best = 0;
            float bs = -INFINITY;
#pragma unroll
            for (int n = 0; n < NN; ++n) {
                float sc = logf(e[n] / es) + gum[((size_t)d * NB + b) * NN + n];
                if (sc > bs) { bs = sc; best = n; }
            }
            sik = best;
        }
        __syncthreads();
        ik = sik;

        // store offset & scale for the output pass
        g_A[((size_t)d * NB + b) * ND + i] = cacc;
        g_S[((size_t)d * NB + b) * ND + i] = vds[d][((size_t)node * NN + ik) * ND + i];
        node = node * NN + ik;
    }
}

// ---------------------------------------------------------------------------
// Kernel 3: streaming output. out[d,b,t,:] = (x[b,t,:] + A[d,b,:]) * S[d,b,:]
// grid = (NT/TT, NB), blockDim = (128, 2). Thread owns a fixed float4 dim
// group -> A/S live in 24 registers; loop over timesteps.
// ---------------------------------------------------------------------------
__global__ void out_kernel(const float* __restrict__ x, float* __restrict__ out) {
    int b = blockIdx.y;
    int g = threadIdx.x;                // float4 dim group 0..127
    int t0 = blockIdx.x * TT + threadIdx.y;

    const float4* A4 = (const float4*)g_A;
    const float4* S4 = (const float4*)g_S;
    int off = b * (ND / 4) + g;
    float4 a0 = A4[0 * NB * (ND / 4) + off];
    float4 a1 = A4[1 * NB * (ND / 4) + off];
    float4 a2 = A4[2 * NB * (ND / 4) + off];
    float4 s0 = S4[0 * NB * (ND / 4) + off];
    float4 s1 = S4[1 * NB * (ND / 4) + off];
    float4 s2 = S4[2 * NB * (ND / 4) + off];

    const float4* xp = (const float4*)x;
    float4* op = (float4*)out;
    const size_t stride_d = (size_t)NB * NT * (ND / 4);
    const size_t brow = (size_t)b * NT * (ND / 4);

#pragma unroll 4
    for (int t = t0; t < t0 + TT; t += 2) {
        size_t idx = brow + (size_t)t * (ND / 4) + g;
        float4 v = xp[idx];
        float4 r0, r1, r2;
        r0.x = (v.x + a0.x) * s0.x; r0.y = (v.y + a0.y) * s0.y;
        r0.z = (v.z + a0.z) * s0.z; r0.w = (v.w + a0.w) * s0.w;
        r1.x = (v.x + a1.x) * s1.x; r1.y = (v.y + a1.y) * s1.y;
        r1.z = (v.z + a1.z) * s1.z; r1.w = (v.w + a1.w) * s1.w;
        r2.x = (v.x + a2.x) * s2.x; r2.y = (v.y + a2.y) * s2.y;
        r2.z = (v.z + a2.z) * s2.z; r2.w = (v.w + a2.w) * s2.w;
        op[idx] = r0;
        op[idx + stride_d] = r1;
        op[idx + 2 * stride_d] = r2;
    }
}

// ---------------------------------------------------------------------------
extern "C" void kernel_launch(void* const* d_in, const int* in_sizes, int n_in,
                              void* d_out, int out_size) {
    const float* x   = (const float*)d_in[0];
    const float* kd0 = (const float*)d_in[1];
    const float* kd1 = (const float*)d_in[2];
    const float* kd2 = (const float*)d_in[3];
    const float* vd0 = (const float*)d_in[4];
    const float* vd1 = (const float*)d_in[5];
    const float* vd2 = (const float*)d_in[6];
    const float* W   = (const float*)d_in[7];
    const float* gum = (const float*)d_in[8];
    float* out = (float*)d_out;

    pool_kernel<<<NB * NCHUNK, 128>>>(x);
    decide_kernel<<<NB, ND>>>(kd0, kd1, kd2, vd0, vd1, vd2, W, gum);
    out_kernel<<<dim3(NT / TT, NB), dim3(128, 2)>>>(x, out);
}

// round 2
// speedup vs baseline: 1.0987x; 1.0987x over previous
#include <cuda_runtime.h>
#include <math.h>

#define NB 32
#define NT 1024
#define ND 512
#define NN 16
#define NDEPTH 3
#define NCHUNK 64
#define TC (NT / NCHUNK)   // 16 timesteps per partial-sum chunk
#define TT 16              // timesteps per output block

// Scratch (static device globals — no allocation)
__device__ float g_partial[NB * NCHUNK * ND];      // 4 MB partial sums
__device__ float g_A[NDEPTH * NB * ND];            // per-depth additive offset c_d[b,:]
__device__ float g_S[NDEPTH * NB * ND];            // per-depth scale sel_d[b,:]

// ---------------------------------------------------------------------------
// Kernel 1: partial sums of x over T (deterministic fixed-order, no atomics).
// grid = NB*NCHUNK = 2048 blocks, 128 threads; each thread owns a float4
// dim-group and sums TC=16 timesteps.
// ---------------------------------------------------------------------------
__global__ void pool_kernel(const float* __restrict__ x) {
    int blk = blockIdx.x;               // b * NCHUNK + chunk
    int b = blk >> 6;                   // / NCHUNK
    int c = blk & (NCHUNK - 1);
    int g = threadIdx.x;                // 0..127 (float4 group over DIM)
    const float4* xp = (const float4*)(x) + ((size_t)b * NT + (size_t)c * TC) * (ND / 4) + g;
    float4 acc = make_float4(0.f, 0.f, 0.f, 0.f);
#pragma unroll
    for (int t = 0; t < TC; ++t) {
        float4 v = xp[(size_t)t * (ND / 4)];
        acc.x += v.x; acc.y += v.y; acc.z += v.z; acc.w += v.w;
    }
    ((float4*)g_partial)[(size_t)blk * (ND / 4) + g] = acc;
}

// ---------------------------------------------------------------------------
// Kernel 2: per-batch decision chain. grid = NB blocks, 512 threads (= DIM).
// Sequential over DEPTH: logits -> softmax -> log+gumbel argmax -> route.
// Stores per-depth offset (A) and scale (S) vectors.
// ---------------------------------------------------------------------------
__global__ void decide_kernel(const float* __restrict__ kd0,
                              const float* __restrict__ kd1,
                              const float* __restrict__ kd2,
                              const float* __restrict__ vd0,
                              const float* __restrict__ vd1,
                              const float* __restrict__ vd2,
                              const float* __restrict__ W,
                              const float* __restrict__ gum) {
    int b = blockIdx.x;
    int i = threadIdx.x;                // 0..511 (dim)
    int lane = i & 31;
    int wid = i >> 5;                   // 0..15 (one warp per node n)

    __shared__ float sp[ND];
    __shared__ float slog[NN];
    __shared__ int   sik;

    // pooled_base[b,i] = mean_t x[b,t,i]  (fixed-order chunk sum)
    float pooled = 0.f;
#pragma unroll
    for (int c = 0; c < NCHUNK; ++c)
        pooled += g_partial[(size_t)(b * NCHUNK + c) * ND + i];
    pooled *= (1.0f / NT);

    const float* kds[NDEPTH] = {kd0, kd1, kd2};
    const float* vds[NDEPTH] = {vd0, vd1, vd2};

    float cacc = 0.f;   // cumulative W-row offset for this dim
    int node = 0;
    int ik = 0;

    for (int d = 0; d < NDEPTH; ++d) {
        if (d > 0) cacc += W[(size_t)ik * ND + i];
        sp[i] = pooled + cacc;
        __syncthreads();

        // warp `wid` computes logits[wid] = dot(sp, keys[d][node, wid, :])
        const float* krow = kds[d] + ((size_t)node * NN + wid) * ND;
        float s = 0.f;
#pragma unroll
        for (int j = lane; j < ND; j += 32) s += sp[j] * krow[j];
#pragma unroll
        for (int o = 16; o; o >>= 1) s += __shfl_down_sync(0xffffffffu, s, o);
        if (lane == 0) slog[wid] = s;
        __syncthreads();

        if (i == 0) {
            // softmax over NN, then argmax(log(prob) + gumbel) — first-max wins (matches jnp.argmax)
            float m = slog[0];
#pragma unroll
            for (int n = 1; n < NN; ++n) m = fmaxf(m, slog[n]);
            float e[NN];
            float es = 0.f;
#pragma unroll
            for (int n = 0; n < NN; ++n) { e[n] = expf(slog[n] - m); es += e[n]; }
            int best = 0;
            float bs = -INFINITY;
#pragma unroll
            for (int n = 0; n < NN; ++n) {
                float sc = logf(e[n] / es) + gum[((size_t)d * NB + b) * NN + n];
                if (sc > bs) { bs = sc; best = n; }
            }
            sik = best;
        }
        __syncthreads();
        ik = sik;

        // store offset & scale for the output pass
        g_A[((size_t)d * NB + b) * ND + i] = cacc;
        g_S[((size_t)d * NB + b) * ND + i] = vds[d][((size_t)node * NN + ik) * ND + i];
        node = node * NN + ik;
    }
}

// ---------------------------------------------------------------------------
// Kernel 3: streaming output. out[d,b,t,:] = (x[b,t,:] + A[d,b,:]) * S[d,b,:]
// grid = (NT/TT, NB), blockDim = (128, 2). Thread owns a fixed float4 dim
// group -> A/S live in 24 registers; loop over timesteps. Output stores use
// __stcs (evict-first) so the 201MB of writes don't evict x from L2.
// ---------------------------------------------------------------------------
__global__ void out_kernel(const float* __restrict__ x, float* __restrict__ out) {
    int b = blockIdx.y;
    int g = threadIdx.x;                // float4 dim group 0..127
    int t0 = blockIdx.x * TT + threadIdx.y;

    const float4* A4 = (const float4*)g_A;
    const float4* S4 = (const float4*)g_S;
    int off = b * (ND / 4) + g;
    float4 a0 = A4[0 * NB * (ND / 4) + off];
    float4 a1 = A4[1 * NB * (ND / 4) + off];
    float4 a2 = A4[2 * NB * (ND / 4) + off];
    float4 s0 = S4[0 * NB * (ND / 4) + off];
    float4 s1 = S4[1 * NB * (ND / 4) + off];
    float4 s2 = S4[2 * NB * (ND / 4) + off];

    const float4* xp = (const float4*)x;
    float4* op = (float4*)out;
    const size_t stride_d = (size_t)NB * NT * (ND / 4);
    const size_t brow = (size_t)b * NT * (ND / 4);

#pragma unroll
    for (int t = t0; t < t0 + TT; t += 2) {
        size_t idx = brow + (size_t)t * (ND / 4) + g;
        float4 v = xp[idx];
        float4 r0, r1, r2;
        r0.x = (v.x + a0.x) * s0.x; r0.y = (v.y + a0.y) * s0.y;
        r0.z = (v.z + a0.z) * s0.z; r0.w = (v.w + a0.w) * s0.w;
        r1.x = (v.x + a1.x) * s1.x; r1.y = (v.y + a1.y) * s1.y;
        r1.z = (v.z + a1.z) * s1.z; r1.w = (v.w + a1.w) * s1.w;
        r2.x = (v.x + a2.x) * s2.x; r2.y = (v.y + a2.y) * s2.y;
        r2.z = (v.z + a2.z) * s2.z; r2.w = (v.w + a2.w) * s2.w;
        __stcs(&op[idx], r0);
        __stcs(&op[idx + stride_d], r1);
        __stcs(&op[idx + 2 * stride_d], r2);
    }
}

// ---------------------------------------------------------------------------
extern "C" void kernel_launch(void* const* d_in, const int* in_sizes, int n_in,
                              void* d_out, int out_size) {
    const float* x   = (const float*)d_in[0];
    const float* kd0 = (const float*)d_in[1];
    const float* kd1 = (const float*)d_in[2];
    const float* kd2 = (const float*)d_in[3];
    const float* vd0 = (const float*)d_in[4];
    const float* vd1 = (const float*)d_in[5];
    const float* vd2 = (const float*)d_in[6];
    const float* W   = (const float*)d_in[7];
    const float* gum = (const float*)d_in[8];
    float* out = (float*)d_out;

    pool_kernel<<<NB * NCHUNK, 128>>>(x);
    decide_kernel<<<NB, ND>>>(kd0, kd1, kd2, vd0, vd1, vd2, W, gum);
    out_kernel<<<dim3(NT / TT, NB), dim3(128, 2)>>>(x, out);
}

// round 3
// speedup vs baseline: 1.1850x; 1.0785x over previous
#include <cuda_runtime.h>
#include <math.h>

#define NB 32
#define NT 1024
#define ND 512
#define NN 16
#define NDEPTH 3
#define NCHUNK 64
#define TC (NT / NCHUNK)   // 16 timesteps per partial-sum chunk
#define TT 16              // timesteps per output block

// Scratch (static device globals — no allocation)
__device__ float g_partial[NB * NCHUNK * ND];      // 4 MB partial sums
__device__ float g_A[NDEPTH * NB * ND];            // per-depth additive offset c_d[b,:]
__device__ float g_S[NDEPTH * NB * ND];            // per-depth scale sel_d[b,:]

// ---------------------------------------------------------------------------
// Kernel 1: partial sums of x over T. All 16 loads front-batched into a
// register array (high MLP), then tree-summed. grid = NB*NCHUNK = 2048.
// ---------------------------------------------------------------------------
__global__ void __launch_bounds__(128) pool_kernel(const float* __restrict__ x) {
    int blk = blockIdx.x;               // b * NCHUNK + chunk
    int b = blk >> 6;                   // / NCHUNK
    int c = blk & (NCHUNK - 1);
    int g = threadIdx.x;                // 0..127 (float4 group over DIM)
    const float4* xp = (const float4*)(x) + ((size_t)b * NT + (size_t)c * TC) * (ND / 4) + g;

    float4 v[TC];
#pragma unroll
    for (int t = 0; t < TC; ++t)
        v[t] = xp[(size_t)t * (ND / 4)];

    // pairwise tree sum (keeps all loads independent & front-batched)
#pragma unroll
    for (int s = TC / 2; s > 0; s >>= 1)
#pragma unroll
        for (int t = 0; t < s; ++t) {
            v[t].x += v[t + s].x; v[t].y += v[t + s].y;
            v[t].z += v[t + s].z; v[t].w += v[t + s].w;
        }

    ((float4*)g_partial)[(size_t)blk * (ND / 4) + g] = v[0];
}

// ---------------------------------------------------------------------------
// Kernel 2: per-batch decision chain. grid = NB blocks, 512 threads (= DIM).
// ---------------------------------------------------------------------------
__global__ void decide_kernel(const float* __restrict__ kd0,
                              const float* __restrict__ kd1,
                              const float* __restrict__ kd2,
                              const float* __restrict__ vd0,
                              const float* __restrict__ vd1,
                              const float* __restrict__ vd2,
                              const float* __restrict__ W,
                              const float* __restrict__ gum) {
    int b = blockIdx.x;
    int i = threadIdx.x;                // 0..511 (dim)
    int lane = i & 31;
    int wid = i >> 5;                   // 0..15 (one warp per node n)

    __shared__ float sp[ND];
    __shared__ float slog[NN];
    __shared__ int   sik;

    // pooled_base[b,i] = mean_t x[b,t,i]  — batched loads (8 in flight)
    float pooled = 0.f;
#pragma unroll
    for (int c0 = 0; c0 < NCHUNK; c0 += 8) {
        float p[8];
#pragma unroll
        for (int j = 0; j < 8; ++j)
            p[j] = g_partial[(size_t)(b * NCHUNK + c0 + j) * ND + i];
#pragma unroll
        for (int j = 0; j < 8; ++j) pooled += p[j];
    }
    pooled *= (1.0f / NT);

    const float* kds[NDEPTH] = {kd0, kd1, kd2};
    const float* vds[NDEPTH] = {vd0, vd1, vd2};

    float cacc = 0.f;   // cumulative W-row offset for this dim
    int node = 0;
    int ik = 0;

    for (int d = 0; d < NDEPTH; ++d) {
        if (d > 0) cacc += W[(size_t)ik * ND + i];
        sp[i] = pooled + cacc;
        __syncthreads();

        // warp `wid` computes logits[wid] = dot(sp, keys[d][node, wid, :])
        const float* krow = kds[d] + ((size_t)node * NN + wid) * ND;
        float s = 0.f;
#pragma unroll
        for (int j = lane; j < ND; j += 32) s += sp[j] * krow[j];
#pragma unroll
        for (int o = 16; o; o >>= 1) s += __shfl_down_sync(0xffffffffu, s, o);
        if (lane == 0) slog[wid] = s;
        __syncthreads();

        if (i == 0) {
            // softmax over NN, then argmax(log(prob) + gumbel) — first-max wins
            float m = slog[0];
#pragma unroll
            for (int n = 1; n < NN; ++n) m = fmaxf(m, slog[n]);
            float e[NN];
            float es = 0.f;
#pragma unroll
            for (int n = 0; n < NN; ++n) { e[n] = expf(slog[n] - m); es += e[n]; }
            int best = 0;
            float bs = -INFINITY;
#pragma unroll
            for (int n = 0; n < NN; ++n) {
                float sc = logf(e[n] / es) + gum[((size_t)d * NB + b) * NN + n];
                if (sc > bs) { bs = sc; best = n; }
            }
            sik = best;
        }
        __syncthreads();
        ik = sik;

        // store offset & scale for the output pass
        g_A[((size_t)d * NB + b) * ND + i] = cacc;
        g_S[((size_t)d * NB + b) * ND + i] = vds[d][((size_t)node * NN + ik) * ND + i];
        node = node * NN + ik;
    }
}

// ---------------------------------------------------------------------------
// Kernel 3: streaming output. out[d,b,t,:] = (x[b,t,:] + A[d,b,:]) * S[d,b,:]
// Batched: 8 independent LDG.128 issued first (high read MLP), then 24
// evict-first STG.128. grid = (NT/TT, NB), blockDim = (128, 2); each thread
// owns a fixed float4 dim group and 8 consecutive timesteps.
// ---------------------------------------------------------------------------
__global__ void __launch_bounds__(256) out_kernel(const float* __restrict__ x,
                                                  float* __restrict__ out) {
    int b = blockIdx.y;
    int g = threadIdx.x;                // float4 dim group 0..127
    int t0 = blockIdx.x * TT + threadIdx.y * (TT / 2);   // 8 consecutive t's

    const float4* A4 = (const float4*)g_A;
    const float4* S4 = (const float4*)g_S;
    int off = b * (ND / 4) + g;
    float4 a0 = A4[0 * NB * (ND / 4) + off];
    float4 a1 = A4[1 * NB * (ND / 4) + off];
    float4 a2 = A4[2 * NB * (ND / 4) + off];
    float4 s0 = S4[0 * NB * (ND / 4) + off];
    float4 s1 = S4[1 * NB * (ND / 4) + off];
    float4 s2 = S4[2 * NB * (ND / 4) + off];

    const float4* xp = (const float4*)x;
    float4* op = (float4*)out;
    const size_t stride_d = (size_t)NB * NT * (ND / 4);
    const size_t base = ((size_t)b * NT + t0) * (ND / 4) + g;

    float4 v[8];
#pragma unroll
    for (int i = 0; i < 8; ++i)
        v[i] = xp[base + (size_t)i * (ND / 4)];

#pragma unroll
    for (int i = 0; i < 8; ++i) {
        size_t idx = base + (size_t)i * (ND / 4);
        float4 r0, r1, r2;
        r0.x = (v[i].x + a0.x) * s0.x; r0.y = (v[i].y + a0.y) * s0.y;
        r0.z = (v[i].z + a0.z) * s0.z; r0.w = (v[i].w + a0.w) * s0.w;
        r1.x = (v[i].x + a1.x) * s1.x; r1.y = (v[i].y + a1.y) * s1.y;
        r1.z = (v[i].z + a1.z) * s1.z; r1.w = (v[i].w + a1.w) * s1.w;
        r2.x = (v[i].x + a2.x) * s2.x; r2.y = (v[i].y + a2.y) * s2.y;
        r2.z = (v[i].z + a2.z) * s2.z; r2.w = (v[i].w + a2.w) * s2.w;
        __stcs(&op[idx], r0);
        __stcs(&op[idx + stride_d], r1);
        __stcs(&op[idx + 2 * stride_d], r2);
    }
}

// ---------------------------------------------------------------------------
extern "C" void kernel_launch(void* const* d_in, const int* in_sizes, int n_in,
                              void* d_out, int out_size) {
    const float* x   = (const float*)d_in[0];
    const float* kd0 = (const float*)d_in[1];
    const float* kd1 = (const float*)d_in[2];
    const float* kd2 = (const float*)d_in[3];
    const float* vd0 = (const float*)d_in[4];
    const float* vd1 = (const float*)d_in[5];
    const float* vd2 = (const float*)d_in[6];
    const float* W   = (const float*)d_in[7];
    const float* gum = (const float*)d_in[8];
    float* out = (float*)d_out;

    pool_kernel<<<NB * NCHUNK, 128>>>(x);
    decide_kernel<<<NB, ND>>>(kd0, kd1, kd2, vd0, vd1, vd2, W, gum);
    out_kernel<<<dim3(NT / TT, NB), dim3(128, 2)>>>(x, out);
}